// round 8
// baseline (speedup 1.0000x reference)
#include <cuda_runtime.h>
#include <cstdint>

#define NN 100000
#define EE 1200000

// Scratch: aggregated messages per node [N, 64].
// Zero-initialized at module load; the MLP kernel re-zeroes its tile every
// call, so the buffer is always zero at kernel_launch entry (graph-replay safe).
__device__ float g_agg[NN * 64];

// ---------------------------------------------------------------------------
// Kernel 1: scatter-add  agg[dst] += node_feat[src] + edge_feat[e]
// 16 threads per edge, one float4 chunk each (best measured variant).
// ---------------------------------------------------------------------------
__global__ void scatter_kernel(const float* __restrict__ node_feat,
                               const float* __restrict__ edge_feat,
                               const int* __restrict__ ei, int E) {
    int gid = blockIdx.x * blockDim.x + threadIdx.x;
    if (gid >= E * 16) return;
    int e = gid >> 4;
    int c = gid & 15;
    int s = __ldg(ei + e);
    int d = __ldg(ei + E + e);
    float4 nf = __ldg(((const float4*)node_feat) + s * 16 + c);
    float4 ef = __ldg(((const float4*)edge_feat) + (size_t)e * 16 + c);
    float4 m = make_float4(nf.x + ef.x, nf.y + ef.y, nf.z + ef.z, nf.w + ef.w);
    float* p = g_agg + (size_t)d * 64 + (c << 2);
    asm volatile("red.global.add.v4.f32 [%0], {%1, %2, %3, %4};"
                 :: "l"(p), "f"(m.x), "f"(m.y), "f"(m.z), "f"(m.w)
                 : "memory");
}

// ---------------------------------------------------------------------------
// Packed f32x2 helpers
// ---------------------------------------------------------------------------
__device__ __forceinline__ unsigned long long fma2(unsigned long long a,
                                                   unsigned long long b,
                                                   unsigned long long c) {
    unsigned long long d;
    asm("fma.rn.f32x2 %0, %1, %2, %3;" : "=l"(d) : "l"(a), "l"(b), "l"(c));
    return d;
}
__device__ __forceinline__ unsigned long long pack2(float x, float y) {
    unsigned long long d;
    asm("mov.b64 %0, {%1, %2};" : "=l"(d) : "f"(x), "f"(y));
    return d;
}
__device__ __forceinline__ void unpack2(unsigned long long v, float& x, float& y) {
    asm("mov.b64 {%0, %1}, %2;" : "=f"(x), "=f"(y) : "l"(v));
}

// ---------------------------------------------------------------------------
// Kernel 2: fused MLP. BM=64 nodes/block, 256 threads, 3 blocks/SM.
// Weights read via broadcast LDG.128 (L1-resident, 96KB). Smem holds only
// the activation tiles: aT[64][68] (phase A) aliased under Hs[128][68].
// GEMM1: 4m x 8j per thread. GEMM2: 4m x 4j per thread.
// ---------------------------------------------------------------------------
#define BM 64
#define MLP_THREADS 256
#define AT_S 68
#define HS_S 68
#define SM_FLOATS (128 * HS_S)   // 8704 floats = 34816 B

__global__ void __launch_bounds__(MLP_THREADS, 3) mlp_kernel(
    const float* __restrict__ W1, const float* __restrict__ b1,
    const float* __restrict__ W2, const float* __restrict__ b2,
    float* __restrict__ out, int N) {
    __shared__ float sm[SM_FLOATS];
    float* aT = sm;               // [64][AT_S], dead after GEMM1
    float* Hs = sm;               // [128][HS_S], written after barrier
    int tid = threadIdx.x;
    int node0 = blockIdx.x * BM;

    // Stage agg tile transposed: aT[k][m] = agg[node0+m][k]   (64 x 64)
#pragma unroll
    for (int i = 0; i < 4; i++) {
        int f = tid + i * 256;          // float4 id 0..1023
        int r = f >> 4;                 // node in tile 0..63
        int c4 = f & 15;
        int n = node0 + r;
        float4 v = (n < N) ? __ldg(((const float4*)g_agg) + (size_t)n * 16 + c4)
                           : make_float4(0.f, 0.f, 0.f, 0.f);
        int c = c4 * 4;
        aT[(c + 0) * AT_S + r] = v.x;
        aT[(c + 1) * AT_S + r] = v.y;
        aT[(c + 2) * AT_S + r] = v.z;
        aT[(c + 3) * AT_S + r] = v.w;
    }
    __syncthreads();

    // Re-zero our slice of g_agg (invariant restore); overlaps GEMM1.
#pragma unroll
    for (int i = 0; i < 4; i++) {
        int f = tid + i * 256;
        int n = node0 + (f >> 4);
        if (n < N)
            ((float4*)g_agg)[(size_t)n * 16 + (f & 15)] =
                make_float4(0.f, 0.f, 0.f, 0.f);
    }

    int mg = tid & 15;
    int jg = tid >> 4;
    int m0 = mg * 4;

    // ---------------- GEMM1: H = relu(A @ W1 + b1), 4m x 8j ----------------
    {
        int j0 = jg * 8;
        unsigned long long acc[4][4];
        {
            float4 blo = __ldg((const float4*)(b1 + j0));
            float4 bhi = __ldg((const float4*)(b1 + j0 + 4));
            unsigned long long bj[4] = { pack2(blo.x, blo.y), pack2(blo.z, blo.w),
                                         pack2(bhi.x, bhi.y), pack2(bhi.z, bhi.w) };
#pragma unroll
            for (int m = 0; m < 4; m++)
#pragma unroll
                for (int p = 0; p < 4; p++) acc[m][p] = bj[p];
        }
#pragma unroll 4
        for (int k = 0; k < 64; k++) {
            float4 av = *(const float4*)(aT + k * AT_S + m0);
            float4 w0 = __ldg((const float4*)(W1 + k * 128 + j0));
            float4 w1 = __ldg((const float4*)(W1 + k * 128 + j0 + 4));
            unsigned long long wv[4] = { pack2(w0.x, w0.y), pack2(w0.z, w0.w),
                                         pack2(w1.x, w1.y), pack2(w1.z, w1.w) };
            float a4[4] = { av.x, av.y, av.z, av.w };
#pragma unroll
            for (int m = 0; m < 4; m++) {
                unsigned long long am = pack2(a4[m], a4[m]);
#pragma unroll
                for (int p = 0; p < 4; p++)
                    acc[m][p] = fma2(am, wv[p], acc[m][p]);
            }
        }
        __syncthreads();    // aT reads done -> safe to alias with Hs

        // ReLU -> Hs[j][m] (float4 stores, 16B aligned: HS_S*4=272, m0*4)
#pragma unroll
        for (int p = 0; p < 4; p++) {
#pragma unroll
            for (int h = 0; h < 2; h++) {
                float v4[4];
#pragma unroll
                for (int m = 0; m < 4; m++) {
                    float x, y;
                    unpack2(acc[m][p], x, y);
                    v4[m] = fmaxf(h == 0 ? x : y, 0.f);
                }
                int j = j0 + 2 * p + h;
                *(float4*)(Hs + j * HS_S + m0) = make_float4(v4[0], v4[1], v4[2], v4[3]);
            }
        }
    }
    __syncthreads();

    // ---------------- GEMM2: out = H @ W2 + b2, 4m x 4j ----------------
    {
        int j0 = jg * 4;
        unsigned long long acc2[4][2];
        {
            float4 bv = __ldg((const float4*)(b2 + j0));
            unsigned long long bA = pack2(bv.x, bv.y), bB = pack2(bv.z, bv.w);
#pragma unroll
            for (int m = 0; m < 4; m++) { acc2[m][0] = bA; acc2[m][1] = bB; }
        }
#pragma unroll 4
        for (int k = 0; k < 128; k++) {
            float4 hv = *(const float4*)(Hs + k * HS_S + m0);
            float4 w4 = __ldg((const float4*)(W2 + k * 64 + j0));
            unsigned long long wv[2] = { pack2(w4.x, w4.y), pack2(w4.z, w4.w) };
            float h4[4] = { hv.x, hv.y, hv.z, hv.w };
#pragma unroll
            for (int m = 0; m < 4; m++) {
                unsigned long long hm = pack2(h4[m], h4[m]);
                acc2[m][0] = fma2(hm, wv[0], acc2[m][0]);
                acc2[m][1] = fma2(hm, wv[1], acc2[m][1]);
            }
        }
#pragma unroll
        for (int m = 0; m < 4; m++) {
            int n = node0 + m0 + m;
            if (n < N) {
                float4 v;
                unpack2(acc2[m][0], v.x, v.y);
                unpack2(acc2[m][1], v.z, v.w);
                *(float4*)(out + (size_t)n * 64 + j0) = v;
            }
        }
    }
}

// ---------------------------------------------------------------------------
// Launch: scatter -> MLP (MLP restores the zero invariant on g_agg)
// ---------------------------------------------------------------------------
extern "C" void kernel_launch(void* const* d_in, const int* in_sizes, int n_in,
                              void* d_out, int out_size) {
    const float* node_feat = (const float*)d_in[0];
    const float* edge_feat = (const float*)d_in[1];
    const int*   ei        = (const int*)d_in[2];
    const float* W1        = (const float*)d_in[3];
    const float* b1        = (const float*)d_in[4];
    const float* W2        = (const float*)d_in[5];
    const float* b2        = (const float*)d_in[6];
    float* out = (float*)d_out;

    int N = in_sizes[0] / 64;   // 100000
    int E = in_sizes[2] / 2;    // 1200000

    scatter_kernel<<<(E * 16 + 255) / 256, 256>>>(node_feat, edge_feat, ei, E);
    mlp_kernel<<<(N + BM - 1) / BM, MLP_THREADS>>>(W1, b1, W2, b2, out, N);
}

// round 9
// speedup vs baseline: 1.0871x; 1.0871x over previous
#include <cuda_runtime.h>
#include <cstdint>

#define NN 100000
#define EE 1200000

// Scratch: aggregated messages per node [N, 64].
// Zero-initialized at module load; the MLP kernel re-zeroes its tile every
// call, so the buffer is always zero at kernel_launch entry (graph-replay safe).
__device__ float g_agg[NN * 64];

// ---------------------------------------------------------------------------
// Kernel 1: scatter-add  agg[dst] += node_feat[src] + edge_feat[e]
// 16 threads per edge, one float4 chunk each (best measured variant).
// ---------------------------------------------------------------------------
__global__ void scatter_kernel(const float* __restrict__ node_feat,
                               const float* __restrict__ edge_feat,
                               const int* __restrict__ ei, int E) {
    int gid = blockIdx.x * blockDim.x + threadIdx.x;
    if (gid >= E * 16) return;
    int e = gid >> 4;
    int c = gid & 15;
    int s = __ldg(ei + e);
    int d = __ldg(ei + E + e);
    float4 nf = __ldg(((const float4*)node_feat) + s * 16 + c);
    float4 ef = __ldg(((const float4*)edge_feat) + (size_t)e * 16 + c);
    float4 m = make_float4(nf.x + ef.x, nf.y + ef.y, nf.z + ef.z, nf.w + ef.w);
    float* p = g_agg + (size_t)d * 64 + (c << 2);
    asm volatile("red.global.add.v4.f32 [%0], {%1, %2, %3, %4};"
                 :: "l"(p), "f"(m.x), "f"(m.y), "f"(m.z), "f"(m.w)
                 : "memory");
}

// ---------------------------------------------------------------------------
// Packed f32x2 helpers
// ---------------------------------------------------------------------------
__device__ __forceinline__ unsigned long long fma2(unsigned long long a,
                                                   unsigned long long b,
                                                   unsigned long long c) {
    unsigned long long d;
    asm("fma.rn.f32x2 %0, %1, %2, %3;" : "=l"(d) : "l"(a), "l"(b), "l"(c));
    return d;
}
__device__ __forceinline__ unsigned long long pack2(float x, float y) {
    unsigned long long d;
    asm("mov.b64 %0, {%1, %2};" : "=l"(d) : "f"(x), "f"(y));
    return d;
}
__device__ __forceinline__ void unpack2(unsigned long long v, float& x, float& y) {
    asm("mov.b64 {%0, %1}, %2;" : "=f"(x), "=f"(y) : "l"(v));
}

// ---------------------------------------------------------------------------
// Kernel 2: fused MLP. BM=64 nodes/block, 256 threads, 3 blocks/SM.
// Weights served from smem (broadcast LDS). Full phase aliasing:
//   phase A: W1s [0..8192), aT [8192..12288)      = 48 KB live
//   phase B: Hs  [0..8192), W2s [8192..16384)     = 64 KB live
// 64 KB dynamic smem/block -> 3 blocks/SM (24 warps).
// GEMM1: 4m x 8j. GEMM2: 4m x 4j. No smem padding (stride 64, conflict-free).
// ---------------------------------------------------------------------------
#define BM 64
#define MLP_THREADS 256
#define SMEM_BYTES (16384 * 4)

__global__ void __launch_bounds__(MLP_THREADS, 3) mlp_kernel(
    const float* __restrict__ W1, const float* __restrict__ b1,
    const float* __restrict__ W2, const float* __restrict__ b2,
    float* __restrict__ out, int N) {
    extern __shared__ float sm[];
    float* W1s = sm;            // phase A
    float* aT  = sm + 8192;     // phase A  [64][64]
    float* Hs  = sm;            // phase B  [128][64] (overwrites W1s)
    float* W2s = sm + 8192;     // phase B  (overwrites aT)
    int tid = threadIdx.x;
    int node0 = blockIdx.x * BM;

    // Stage W1 [64][128]
#pragma unroll
    for (int i = 0; i < 8; i++) {
        int f = tid + i * 256;
        ((float4*)W1s)[f] = __ldg(((const float4*)W1) + f);
    }
    // Stage agg tile transposed: aT[k][m] = agg[node0+m][k]  (64 x 64)
#pragma unroll
    for (int i = 0; i < 4; i++) {
        int f = tid + i * 256;          // float4 id 0..1023
        int r = f >> 4;                 // node in tile 0..63
        int c4 = f & 15;
        int n = node0 + r;
        float4 v = (n < N) ? __ldg(((const float4*)g_agg) + (size_t)n * 16 + c4)
                           : make_float4(0.f, 0.f, 0.f, 0.f);
        int c = c4 * 4;
        aT[(c + 0) * 64 + r] = v.x;
        aT[(c + 1) * 64 + r] = v.y;
        aT[(c + 2) * 64 + r] = v.z;
        aT[(c + 3) * 64 + r] = v.w;
    }
    __syncthreads();

    // Re-zero our slice of g_agg (invariant restore); overlaps GEMM1.
#pragma unroll
    for (int i = 0; i < 4; i++) {
        int f = tid + i * 256;
        int n = node0 + (f >> 4);
        if (n < N)
            ((float4*)g_agg)[(size_t)n * 16 + (f & 15)] =
                make_float4(0.f, 0.f, 0.f, 0.f);
    }

    int mg = tid & 15;
    int jg = tid >> 4;
    int m0 = mg * 4;
    int j0 = jg * 8;

    // ---------------- GEMM1: H = relu(A @ W1 + b1), 4m x 8j ----------------
    unsigned long long acc[4][4];
    {
        float4 blo = __ldg((const float4*)(b1 + j0));
        float4 bhi = __ldg((const float4*)(b1 + j0 + 4));
        unsigned long long bj[4] = { pack2(blo.x, blo.y), pack2(blo.z, blo.w),
                                     pack2(bhi.x, bhi.y), pack2(bhi.z, bhi.w) };
#pragma unroll
        for (int m = 0; m < 4; m++)
#pragma unroll
            for (int p = 0; p < 4; p++) acc[m][p] = bj[p];
    }
#pragma unroll 4
    for (int k = 0; k < 64; k++) {
        float4 av = *(const float4*)(aT + k * 64 + m0);
        float4 w0 = *(const float4*)(W1s + k * 128 + j0);
        float4 w1 = *(const float4*)(W1s + k * 128 + j0 + 4);
        unsigned long long wv[4] = { pack2(w0.x, w0.y), pack2(w0.z, w0.w),
                                     pack2(w1.x, w1.y), pack2(w1.z, w1.w) };
        float a4[4] = { av.x, av.y, av.z, av.w };
#pragma unroll
        for (int m = 0; m < 4; m++) {
            unsigned long long am = pack2(a4[m], a4[m]);
#pragma unroll
            for (int p = 0; p < 4; p++)
                acc[m][p] = fma2(am, wv[p], acc[m][p]);
        }
    }
    __syncthreads();    // W1s + aT dead -> phase B may overwrite

    // Stage W2 [128][64] into the region that held aT (+beyond)
#pragma unroll
    for (int i = 0; i < 8; i++) {
        int f = tid + i * 256;
        ((float4*)W2s)[f] = __ldg(((const float4*)W2) + f);
    }
    // ReLU -> Hs[j][m] (overwrites W1s region)
#pragma unroll
    for (int p = 0; p < 4; p++) {
#pragma unroll
        for (int h = 0; h < 2; h++) {
            float v4[4];
#pragma unroll
            for (int m = 0; m < 4; m++) {
                float x, y;
                unpack2(acc[m][p], x, y);
                v4[m] = fmaxf(h == 0 ? x : y, 0.f);
            }
            int j = j0 + 2 * p + h;
            *(float4*)(Hs + j * 64 + m0) = make_float4(v4[0], v4[1], v4[2], v4[3]);
        }
    }
    __syncthreads();

    // ---------------- GEMM2: out = H @ W2 + b2, 4m x 4j ----------------
    {
        int j0b = jg * 4;
        unsigned long long acc2[4][2];
        {
            float4 bv = __ldg((const float4*)(b2 + j0b));
            unsigned long long bA = pack2(bv.x, bv.y), bB = pack2(bv.z, bv.w);
#pragma unroll
            for (int m = 0; m < 4; m++) { acc2[m][0] = bA; acc2[m][1] = bB; }
        }
#pragma unroll 4
        for (int k = 0; k < 128; k++) {
            float4 hv = *(const float4*)(Hs + k * 64 + m0);
            float4 w4 = *(const float4*)(W2s + k * 64 + j0b);
            unsigned long long wv[2] = { pack2(w4.x, w4.y), pack2(w4.z, w4.w) };
            float h4[4] = { hv.x, hv.y, hv.z, hv.w };
#pragma unroll
            for (int m = 0; m < 4; m++) {
                unsigned long long hm = pack2(h4[m], h4[m]);
                acc2[m][0] = fma2(hm, wv[0], acc2[m][0]);
                acc2[m][1] = fma2(hm, wv[1], acc2[m][1]);
            }
        }
#pragma unroll
        for (int m = 0; m < 4; m++) {
            int n = node0 + m0 + m;
            if (n < N) {
                float4 v;
                unpack2(acc2[m][0], v.x, v.y);
                unpack2(acc2[m][1], v.z, v.w);
                *(float4*)(out + (size_t)n * 64 + j0b) = v;
            }
        }
    }
}

// ---------------------------------------------------------------------------
// Launch: scatter -> MLP (MLP restores the zero invariant on g_agg)
// ---------------------------------------------------------------------------
extern "C" void kernel_launch(void* const* d_in, const int* in_sizes, int n_in,
                              void* d_out, int out_size) {
    const float* node_feat = (const float*)d_in[0];
    const float* edge_feat = (const float*)d_in[1];
    const int*   ei        = (const int*)d_in[2];
    const float* W1        = (const float*)d_in[3];
    const float* b1        = (const float*)d_in[4];
    const float* W2        = (const float*)d_in[5];
    const float* b2        = (const float*)d_in[6];
    float* out = (float*)d_out;

    int N = in_sizes[0] / 64;   // 100000
    int E = in_sizes[2] / 2;    // 1200000

    cudaFuncSetAttribute(mlp_kernel, cudaFuncAttributeMaxDynamicSharedMemorySize,
                         SMEM_BYTES);

    scatter_kernel<<<(E * 16 + 255) / 256, 256>>>(node_feat, edge_feat, ei, E);
    mlp_kernel<<<(N + BM - 1) / BM, MLP_THREADS, SMEM_BYTES>>>(W1, b1, W2, b2, out, N);
}

// round 11
// speedup vs baseline: 1.2820x; 1.1792x over previous
#include <cuda_runtime.h>
#include <cuda_bf16.h>
#include <cstdint>

#define NN 100000
#define EE 1200000

// Scratch: aggregated messages per node [N, 64]; zero at entry, MLP re-zeroes.
__device__ float g_agg[NN * 64];

// ---------------------------------------------------------------------------
// Kernel 1: scatter-add (best measured variant: 16 threads/edge, RED.v4)
// ---------------------------------------------------------------------------
__global__ void scatter_kernel(const float* __restrict__ node_feat,
                               const float* __restrict__ edge_feat,
                               const int* __restrict__ ei, int E) {
    int gid = blockIdx.x * blockDim.x + threadIdx.x;
    if (gid >= E * 16) return;
    int e = gid >> 4;
    int c = gid & 15;
    int s = __ldg(ei + e);
    int d = __ldg(ei + E + e);
    float4 nf = __ldg(((const float4*)node_feat) + s * 16 + c);
    float4 ef = __ldg(((const float4*)edge_feat) + (size_t)e * 16 + c);
    float4 m = make_float4(nf.x + ef.x, nf.y + ef.y, nf.z + ef.z, nf.w + ef.w);
    float* p = g_agg + (size_t)d * 64 + (c << 2);
    asm volatile("red.global.add.v4.f32 [%0], {%1, %2, %3, %4};"
                 :: "l"(p), "f"(m.x), "f"(m.y), "f"(m.z), "f"(m.w)
                 : "memory");
}

// ---------------------------------------------------------------------------
// mma.sync / ldmatrix helpers (PTX ISA sm_80+, valid under target sm_103)
// ---------------------------------------------------------------------------
__device__ __forceinline__ uint32_t smem_u32(const void* p) {
    uint32_t a;
    asm("{ .reg .u64 t; cvta.to.shared.u64 t, %1; cvt.u32.u64 %0, t; }"
        : "=r"(a) : "l"(p));
    return a;
}

#define LDMX4(d0, d1, d2, d3, addr) \
    asm volatile("ldmatrix.sync.aligned.m8n8.x4.shared.b16 {%0,%1,%2,%3}, [%4];" \
                 : "=r"(d0), "=r"(d1), "=r"(d2), "=r"(d3) : "r"(addr))

#define MMA16816(c, a0, a1, a2, a3, b0, b1) \
    asm volatile("mma.sync.aligned.m16n8k16.row.col.f32.bf16.bf16.f32 " \
                 "{%0,%1,%2,%3}, {%4,%5,%6,%7}, {%8,%9}, {%0,%1,%2,%3};" \
                 : "+f"((c)[0]), "+f"((c)[1]), "+f"((c)[2]), "+f"((c)[3]) \
                 : "r"(a0), "r"(a1), "r"(a2), "r"(a3), "r"(b0), "r"(b1))

// Store (x0, x1) as bf16-hi pair at column k and bf16-residual pair at k+lo_off.
__device__ __forceinline__ void st_hilo2(uint32_t base, int stride, int row,
                                         int k, int lo_off, float x0, float x1) {
    __nv_bfloat16 h0 = __float2bfloat16(x0), h1 = __float2bfloat16(x1);
    __nv_bfloat16 g0 = __float2bfloat16(x0 - __bfloat162float(h0));
    __nv_bfloat16 g1 = __float2bfloat16(x1 - __bfloat162float(h1));
    uint32_t hw = (uint32_t)__bfloat16_as_ushort(h0) |
                  ((uint32_t)__bfloat16_as_ushort(h1) << 16);
    uint32_t lw = (uint32_t)__bfloat16_as_ushort(g0) |
                  ((uint32_t)__bfloat16_as_ushort(g1) << 16);
    uint32_t a0 = base + (uint32_t)((row * stride + k) * 2);
    uint32_t a1 = base + (uint32_t)((row * stride + k + lo_off) * 2);
    asm volatile("st.shared.b32 [%0], %1;" :: "r"(a0), "r"(hw));
    asm volatile("st.shared.b32 [%0], %1;" :: "r"(a1), "r"(lw));
}

// ---------------------------------------------------------------------------
// Kernel 2: HMMA MLP. 128 nodes/block, 256 threads (8 warps), 2 blocks/SM.
// Error-compensated bf16 split: x = hi + lo (both bf16); drop only lo*lo.
//   Abuf  [128m][136] bf16: cols 0-63 Ahi, 64-127 Alo           @ 0      (34816B)
//   W1buf [128j][136] bf16: cols 0-63 W1hi, 64-127 W1lo         @ 34816  (34816B)
//   Hbuf  [128m][264] bf16: cols 0-127 Hhi, 128-255 Hlo         @ 0      (aliases A+W1)
//   W2buf [64j][264]  bf16: cols 0-127 W2hi, 128-255 W2lo       @ 69632  (33792B)
// GEMM1: 12 k16-steps (AhiWhi, AhiWlo, AloWhi);  GEMM2: 24 steps.
// ---------------------------------------------------------------------------
#define MLP_THREADS 256
#define AS 136
#define HS 264
#define OFF_A  0u
#define OFF_W1 34816u
#define OFF_W2 69632u
#define SMEM_TOTAL 103424

__global__ void __launch_bounds__(MLP_THREADS, 2) mlp_mma_kernel(
    const float* __restrict__ W1, const float* __restrict__ b1,
    const float* __restrict__ W2, const float* __restrict__ b2,
    float* __restrict__ out, int N) {
    extern __shared__ char smc[];
    uint32_t sb = smem_u32(smc);
    int tid = threadIdx.x;
    int lane = tid & 31;
    int wid = tid >> 5;
    int node0 = blockIdx.x * 128;

    // ---- stage A (hi|lo) from g_agg; re-zero g_agg ----
#pragma unroll
    for (int i = 0; i < 8; i++) {
        int f = tid + i * 256;          // 0..2047 float4 ids (128 rows x 16)
        int r = f >> 4, c4 = f & 15;
        int n = node0 + r;
        float4 v = make_float4(0.f, 0.f, 0.f, 0.f);
        if (n < N) {
            v = __ldg(((const float4*)g_agg) + (size_t)n * 16 + c4);
            ((float4*)g_agg)[(size_t)n * 16 + c4] = make_float4(0.f, 0.f, 0.f, 0.f);
        }
        int k = c4 * 4;
        st_hilo2(sb + OFF_A, AS, r, k,     64, v.x, v.y);
        st_hilo2(sb + OFF_A, AS, r, k + 2, 64, v.z, v.w);
    }
    // ---- stage W1' [j][k] = W1[k][j] (hi|lo) ----
#pragma unroll
    for (int i = 0; i < 4; i++) {
        int q = tid + i * 256;          // 0..1023
        int kp = q & 31, j4 = q >> 5;   // k0 = kp*2, j = j4*4
        int k0 = kp * 2;
        float4 wa = __ldg(((const float4*)W1) + k0 * 32 + j4);
        float4 wb = __ldg(((const float4*)W1) + (k0 + 1) * 32 + j4);
        int j = j4 * 4;
        st_hilo2(sb + OFF_W1, AS, j + 0, k0, 64, wa.x, wb.x);
        st_hilo2(sb + OFF_W1, AS, j + 1, k0, 64, wa.y, wb.y);
        st_hilo2(sb + OFF_W1, AS, j + 2, k0, 64, wa.z, wb.z);
        st_hilo2(sb + OFF_W1, AS, j + 3, k0, 64, wa.w, wb.w);
    }
    // ---- stage W2' [j][k] = W2[k][j] (hi|lo) ----
#pragma unroll
    for (int i = 0; i < 4; i++) {
        int q = tid + i * 256;
        int kp = q & 63, j4 = q >> 6;   // k0 = kp*2, j = j4*4
        int k0 = kp * 2;
        float4 wa = __ldg(((const float4*)W2) + k0 * 16 + j4);
        float4 wb = __ldg(((const float4*)W2) + (k0 + 1) * 16 + j4);
        int j = j4 * 4;
        st_hilo2(sb + OFF_W2, HS, j + 0, k0, 128, wa.x, wb.x);
        st_hilo2(sb + OFF_W2, HS, j + 1, k0, 128, wa.y, wb.y);
        st_hilo2(sb + OFF_W2, HS, j + 2, k0, 128, wa.z, wb.z);
        st_hilo2(sb + OFF_W2, HS, j + 3, k0, 128, wa.w, wb.w);
    }
    __syncthreads();

    // Fragment lane offsets (PTX m16n8k16 canonical mappings)
    int rA = (lane & 7) + ((lane >> 3) & 1) * 8;   // A: row += (sel&1)*8
    int cA = (lane >> 4) * 8;                      //    col += (sel>>1)*8
    int rB = (lane & 7) + (lane >> 4) * 8;         // B: row += (sel>>1)*8
    int cB = ((lane >> 3) & 1) * 8;                //    col += (sel&1)*8
    int m0 = wid * 16;
    int g = lane >> 2;
    int cpair = (lane & 3) * 2;

    // ---------------- GEMM1: D1 = Ahi·Whi + Ahi·Wlo + Alo·Whi ----------------
    float acc[16][4];
#pragma unroll
    for (int q = 0; q < 16; q++)
#pragma unroll
        for (int p = 0; p < 4; p++) acc[q][p] = 0.f;

#pragma unroll 4
    for (int s = 0; s < 12; s++) {
        int ka = ((s & 3) << 4) + ((s >= 8) ? 64 : 0);
        int kb = ((s & 3) << 4) + ((s >= 4 && s < 8) ? 64 : 0);
        uint32_t a0, a1, a2, a3;
        LDMX4(a0, a1, a2, a3, sb + OFF_A + (uint32_t)(((m0 + rA) * AS + ka + cA) * 2));
#pragma unroll
        for (int nt = 0; nt < 8; nt++) {
            uint32_t b0, b1r, b2, b3;
            LDMX4(b0, b1r, b2, b3,
                  sb + OFF_W1 + (uint32_t)(((nt * 16 + rB) * AS + kb + cB) * 2));
            MMA16816(acc[2 * nt],     a0, a1, a2, a3, b0, b1r);
            MMA16816(acc[2 * nt + 1], a0, a1, a2, a3, b2, b3);
        }
    }
    __syncthreads();    // Abuf/W1buf dead -> Hbuf may overwrite

    // ---- epilogue 1: +b1, relu, hi/lo split -> Hbuf ----
#pragma unroll
    for (int q = 0; q < 16; q++) {
        int c0 = q * 8 + cpair;
        float bv0 = __ldg(b1 + c0), bv1 = __ldg(b1 + c0 + 1);
        float x0 = fmaxf(acc[q][0] + bv0, 0.f);
        float x1 = fmaxf(acc[q][1] + bv1, 0.f);
        float y0 = fmaxf(acc[q][2] + bv0, 0.f);
        float y1 = fmaxf(acc[q][3] + bv1, 0.f);
        st_hilo2(sb + OFF_A, HS, m0 + g,     c0, 128, x0, x1);
        st_hilo2(sb + OFF_A, HS, m0 + g + 8, c0, 128, y0, y1);
    }
    __syncthreads();

    // ---------------- GEMM2: D2 = Hhi·W2hi + Hlo·W2hi + Hhi·W2lo ----------------
    float acc2[8][4];
#pragma unroll
    for (int q = 0; q < 8; q++)
#pragma unroll
        for (int p = 0; p < 4; p++) acc2[q][p] = 0.f;

#pragma unroll 4
    for (int s = 0; s < 24; s++) {
        int kh = ((s & 7) << 4) + ((s >= 8 && s < 16) ? 128 : 0);
        int kw = ((s & 7) << 4) + ((s >= 16) ? 128 : 0);
        uint32_t a0, a1, a2, a3;
        LDMX4(a0, a1, a2, a3, sb + OFF_A + (uint32_t)(((m0 + rA) * HS + kh + cA) * 2));
#pragma unroll
        for (int nt = 0; nt < 4; nt++) {
            uint32_t b0, b1r, b2, b3;
            LDMX4(b0, b1r, b2, b3,
                  sb + OFF_W2 + (uint32_t)(((nt * 16 + rB) * HS + kw + cB) * 2));
            MMA16816(acc2[2 * nt],     a0, a1, a2, a3, b0, b1r);
            MMA16816(acc2[2 * nt + 1], a0, a1, a2, a3, b2, b3);
        }
    }

    // ---- epilogue 2: +b2 -> out ----
    {
        int n0r = node0 + m0 + g;
        int n1r = n0r + 8;
#pragma unroll
        for (int q = 0; q < 8; q++) {
            int c0 = q * 8 + cpair;
            float bv0 = __ldg(b2 + c0), bv1 = __ldg(b2 + c0 + 1);
            if (n0r < N)
                *(float2*)(out + (size_t)n0r * 64 + c0) =
                    make_float2(acc2[q][0] + bv0, acc2[q][1] + bv1);
            if (n1r < N)
                *(float2*)(out + (size_t)n1r * 64 + c0) =
                    make_float2(acc2[q][2] + bv0, acc2[q][3] + bv1);
        }
    }
}

// ---------------------------------------------------------------------------
// Launch: scatter -> HMMA MLP (MLP restores the zero invariant on g_agg)
// ---------------------------------------------------------------------------
extern "C" void kernel_launch(void* const* d_in, const int* in_sizes, int n_in,
                              void* d_out, int out_size) {
    const float* node_feat = (const float*)d_in[0];
    const float* edge_feat = (const float*)d_in[1];
    const int*   ei        = (const int*)d_in[2];
    const float* W1        = (const float*)d_in[3];
    const float* b1        = (const float*)d_in[4];
    const float* W2        = (const float*)d_in[5];
    const float* b2        = (const float*)d_in[6];
    float* out = (float*)d_out;

    int N = in_sizes[0] / 64;   // 100000
    int E = in_sizes[2] / 2;    // 1200000

    cudaFuncSetAttribute(mlp_mma_kernel, cudaFuncAttributeMaxDynamicSharedMemorySize,
                         SMEM_TOTAL);

    scatter_kernel<<<(E * 16 + 255) / 256, 256>>>(node_feat, edge_feat, ei, E);
    mlp_mma_kernel<<<(N + 127) / 128, MLP_THREADS, SMEM_TOTAL>>>(W1, b1, W2, b2, out, N);
}

// round 12
// speedup vs baseline: 1.3000x; 1.0140x over previous
#include <cuda_runtime.h>
#include <cuda_bf16.h>
#include <cstdint>

#define NN 100000
#define EE 1200000

// Scratch: aggregated messages per node [N, 64]; zero at entry, MLP re-zeroes.
__device__ float g_agg[NN * 64];

// ---------------------------------------------------------------------------
// Kernel 1: scatter-add (best measured variant: 16 threads/edge, RED.v4)
// ---------------------------------------------------------------------------
__global__ void scatter_kernel(const float* __restrict__ node_feat,
                               const float* __restrict__ edge_feat,
                               const int* __restrict__ ei, int E) {
    int gid = blockIdx.x * blockDim.x + threadIdx.x;
    if (gid >= E * 16) return;
    int e = gid >> 4;
    int c = gid & 15;
    int s = __ldg(ei + e);
    int d = __ldg(ei + E + e);
    float4 nf = __ldg(((const float4*)node_feat) + s * 16 + c);
    float4 ef = __ldg(((const float4*)edge_feat) + (size_t)e * 16 + c);
    float4 m = make_float4(nf.x + ef.x, nf.y + ef.y, nf.z + ef.z, nf.w + ef.w);
    float* p = g_agg + (size_t)d * 64 + (c << 2);
    asm volatile("red.global.add.v4.f32 [%0], {%1, %2, %3, %4};"
                 :: "l"(p), "f"(m.x), "f"(m.y), "f"(m.z), "f"(m.w)
                 : "memory");
}

// ---------------------------------------------------------------------------
// mma.sync / ldmatrix helpers
// ---------------------------------------------------------------------------
__device__ __forceinline__ uint32_t smem_u32(const void* p) {
    uint32_t a;
    asm("{ .reg .u64 t; cvta.to.shared.u64 t, %1; cvt.u32.u64 %0, t; }"
        : "=r"(a) : "l"(p));
    return a;
}

#define LDMX4(d0, d1, d2, d3, addr) \
    asm volatile("ldmatrix.sync.aligned.m8n8.x4.shared.b16 {%0,%1,%2,%3}, [%4];" \
                 : "=r"(d0), "=r"(d1), "=r"(d2), "=r"(d3) : "r"(addr))

#define MMA16816(c, a0, a1, a2, a3, b0, b1) \
    asm volatile("mma.sync.aligned.m16n8k16.row.col.f32.bf16.bf16.f32 " \
                 "{%0,%1,%2,%3}, {%4,%5,%6,%7}, {%8,%9}, {%0,%1,%2,%3};" \
                 : "+f"((c)[0]), "+f"((c)[1]), "+f"((c)[2]), "+f"((c)[3]) \
                 : "r"(a0), "r"(a1), "r"(a2), "r"(a3), "r"(b0), "r"(b1))

// Store (x0, x1) as bf16-hi pair at column k and bf16-residual pair at k+lo_off.
__device__ __forceinline__ void st_hilo2(uint32_t base, int stride, int row,
                                         int k, int lo_off, float x0, float x1) {
    __nv_bfloat16 h0 = __float2bfloat16(x0), h1 = __float2bfloat16(x1);
    __nv_bfloat16 g0 = __float2bfloat16(x0 - __bfloat162float(h0));
    __nv_bfloat16 g1 = __float2bfloat16(x1 - __bfloat162float(h1));
    uint32_t hw = (uint32_t)__bfloat16_as_ushort(h0) |
                  ((uint32_t)__bfloat16_as_ushort(h1) << 16);
    uint32_t lw = (uint32_t)__bfloat16_as_ushort(g0) |
                  ((uint32_t)__bfloat16_as_ushort(g1) << 16);
    uint32_t a0 = base + (uint32_t)((row * stride + k) * 2);
    uint32_t a1 = base + (uint32_t)((row * stride + k + lo_off) * 2);
    asm volatile("st.shared.b32 [%0], %1;" :: "r"(a0), "r"(hw));
    asm volatile("st.shared.b32 [%0], %1;" :: "r"(a1), "r"(lw));
}

// ---------------------------------------------------------------------------
// Kernel 2: HMMA MLP. 128 nodes/block, 256 threads (8 warps = 4m x 2j grid).
//   Abuf  [128m][136] bf16: Ahi | Alo                 @ 0      (34816B)
//   W1buf [128j][136] bf16: W1hi | W1lo               @ 34816  (34816B)
//   Hbuf  [128m][264] bf16: Hhi | Hlo                 @ 0      (aliases A+W1)
//   W2buf [64j][264]  bf16: W2hi | W2lo               @ 69632  (33792B)
// Warp tiles: GEMM1 32m x 64j (6 LDSM + 16 MMA / kstep);
//             GEMM2 32m x 32j (4 LDSM + 8 MMA / kstep).
// ---------------------------------------------------------------------------
#define MLP_THREADS 256
#define AS 136
#define HS 264
#define OFF_A  0u
#define OFF_W1 34816u
#define OFF_W2 69632u
#define SMEM_TOTAL 103424

__global__ void __launch_bounds__(MLP_THREADS, 2) mlp_mma_kernel(
    const float* __restrict__ W1, const float* __restrict__ b1,
    const float* __restrict__ W2, const float* __restrict__ b2,
    float* __restrict__ out, int N) {
    extern __shared__ char smc[];
    uint32_t sb = smem_u32(smc);
    int tid = threadIdx.x;
    int lane = tid & 31;
    int wid = tid >> 5;
    int node0 = blockIdx.x * 128;

    // ---- stage A (hi|lo) from g_agg; re-zero g_agg ----
#pragma unroll
    for (int i = 0; i < 8; i++) {
        int f = tid + i * 256;
        int r = f >> 4, c4 = f & 15;
        int n = node0 + r;
        float4 v = make_float4(0.f, 0.f, 0.f, 0.f);
        if (n < N) {
            v = __ldg(((const float4*)g_agg) + (size_t)n * 16 + c4);
            ((float4*)g_agg)[(size_t)n * 16 + c4] = make_float4(0.f, 0.f, 0.f, 0.f);
        }
        int k = c4 * 4;
        st_hilo2(sb + OFF_A, AS, r, k,     64, v.x, v.y);
        st_hilo2(sb + OFF_A, AS, r, k + 2, 64, v.z, v.w);
    }
    // ---- stage W1' [j][k] = W1[k][j] (hi|lo) ----
#pragma unroll
    for (int i = 0; i < 4; i++) {
        int q = tid + i * 256;
        int kp = q & 31, j4 = q >> 5;
        int k0 = kp * 2;
        float4 wa = __ldg(((const float4*)W1) + k0 * 32 + j4);
        float4 wb = __ldg(((const float4*)W1) + (k0 + 1) * 32 + j4);
        int j = j4 * 4;
        st_hilo2(sb + OFF_W1, AS, j + 0, k0, 64, wa.x, wb.x);
        st_hilo2(sb + OFF_W1, AS, j + 1, k0, 64, wa.y, wb.y);
        st_hilo2(sb + OFF_W1, AS, j + 2, k0, 64, wa.z, wb.z);
        st_hilo2(sb + OFF_W1, AS, j + 3, k0, 64, wa.w, wb.w);
    }
    // ---- stage W2' [j][k] = W2[k][j] (hi|lo) ----
#pragma unroll
    for (int i = 0; i < 4; i++) {
        int q = tid + i * 256;
        int kp = q & 63, j4 = q >> 6;
        int k0 = kp * 2;
        float4 wa = __ldg(((const float4*)W2) + k0 * 16 + j4);
        float4 wb = __ldg(((const float4*)W2) + (k0 + 1) * 16 + j4);
        int j = j4 * 4;
        st_hilo2(sb + OFF_W2, HS, j + 0, k0, 128, wa.x, wb.x);
        st_hilo2(sb + OFF_W2, HS, j + 1, k0, 128, wa.y, wb.y);
        st_hilo2(sb + OFF_W2, HS, j + 2, k0, 128, wa.z, wb.z);
        st_hilo2(sb + OFF_W2, HS, j + 3, k0, 128, wa.w, wb.w);
    }
    __syncthreads();

    // Fragment lane offsets (PTX m16n8k16 canonical mappings)
    int rA = (lane & 7) + ((lane >> 3) & 1) * 8;
    int cA = (lane >> 4) * 8;
    int rB = (lane & 7) + (lane >> 4) * 8;
    int cB = ((lane >> 3) & 1) * 8;
    int mw = wid & 3;               // m-warp: rows [mw*32, +32)
    int jw = wid >> 2;              // j-warp
    int m0 = mw * 32;
    int g = lane >> 2;
    int cpair = (lane & 3) * 2;

    // ---------------- GEMM1: D1 = Ahi·Whi + Ahi·Wlo + Alo·Whi ----------------
    // Warp tile 32m x 64j: acc[t(2)][q(8)][4]
    float acc[2][8][4];
#pragma unroll
    for (int t = 0; t < 2; t++)
#pragma unroll
        for (int q = 0; q < 8; q++)
#pragma unroll
            for (int p = 0; p < 4; p++) acc[t][q][p] = 0.f;

    int j0 = jw * 64;
#pragma unroll 4
    for (int s = 0; s < 12; s++) {
        int ka = ((s & 3) << 4) + ((s >= 8) ? 64 : 0);
        int kb = ((s & 3) << 4) + ((s >= 4 && s < 8) ? 64 : 0);
        uint32_t a[2][4];
#pragma unroll
        for (int t = 0; t < 2; t++)
            LDMX4(a[t][0], a[t][1], a[t][2], a[t][3],
                  sb + OFF_A + (uint32_t)(((m0 + t * 16 + rA) * AS + ka + cA) * 2));
#pragma unroll
        for (int nt = 0; nt < 4; nt++) {
            uint32_t b0, b1r, b2, b3;
            LDMX4(b0, b1r, b2, b3,
                  sb + OFF_W1 + (uint32_t)(((j0 + nt * 16 + rB) * AS + kb + cB) * 2));
#pragma unroll
            for (int t = 0; t < 2; t++) {
                MMA16816(acc[t][2 * nt],     a[t][0], a[t][1], a[t][2], a[t][3], b0, b1r);
                MMA16816(acc[t][2 * nt + 1], a[t][0], a[t][1], a[t][2], a[t][3], b2, b3);
            }
        }
    }
    __syncthreads();    // Abuf/W1buf dead -> Hbuf may overwrite

    // ---- epilogue 1: +b1, relu, hi/lo split -> Hbuf ----
#pragma unroll
    for (int t = 0; t < 2; t++) {
#pragma unroll
        for (int q = 0; q < 8; q++) {
            int c0 = j0 + q * 8 + cpair;
            float bv0 = __ldg(b1 + c0), bv1 = __ldg(b1 + c0 + 1);
            float x0 = fmaxf(acc[t][q][0] + bv0, 0.f);
            float x1 = fmaxf(acc[t][q][1] + bv1, 0.f);
            float y0 = fmaxf(acc[t][q][2] + bv0, 0.f);
            float y1 = fmaxf(acc[t][q][3] + bv1, 0.f);
            st_hilo2(sb + OFF_A, HS, m0 + t * 16 + g,     c0, 128, x0, x1);
            st_hilo2(sb + OFF_A, HS, m0 + t * 16 + g + 8, c0, 128, y0, y1);
        }
    }
    __syncthreads();

    // ---------------- GEMM2: D2 = Hhi·W2hi + Hlo·W2hi + Hhi·W2lo ----------------
    // Warp tile 32m x 32j: acc2[t(2)][q(4)][4]
    float acc2[2][4][4];
#pragma unroll
    for (int t = 0; t < 2; t++)
#pragma unroll
        for (int q = 0; q < 4; q++)
#pragma unroll
            for (int p = 0; p < 4; p++) acc2[t][q][p] = 0.f;

    int j0b = jw * 32;
#pragma unroll 4
    for (int s = 0; s < 24; s++) {
        int kh = ((s & 7) << 4) + ((s >= 8 && s < 16) ? 128 : 0);
        int kw = ((s & 7) << 4) + ((s >= 16) ? 128 : 0);
        uint32_t a[2][4];
#pragma unroll
        for (int t = 0; t < 2; t++)
            LDMX4(a[t][0], a[t][1], a[t][2], a[t][3],
                  sb + OFF_A + (uint32_t)(((m0 + t * 16 + rA) * HS + kh + cA) * 2));
#pragma unroll
        for (int nt = 0; nt < 2; nt++) {
            uint32_t b0, b1r, b2, b3;
            LDMX4(b0, b1r, b2, b3,
                  sb + OFF_W2 + (uint32_t)(((j0b + nt * 16 + rB) * HS + kw + cB) * 2));
#pragma unroll
            for (int t = 0; t < 2; t++) {
                MMA16816(acc2[t][2 * nt],     a[t][0], a[t][1], a[t][2], a[t][3], b0, b1r);
                MMA16816(acc2[t][2 * nt + 1], a[t][0], a[t][1], a[t][2], a[t][3], b2, b3);
            }
        }
    }

    // ---- epilogue 2: +b2 -> out ----
#pragma unroll
    for (int t = 0; t < 2; t++) {
        int n0r = node0 + m0 + t * 16 + g;
        int n1r = n0r + 8;
#pragma unroll
        for (int q = 0; q < 4; q++) {
            int c0 = j0b + q * 8 + cpair;
            float bv0 = __ldg(b2 + c0), bv1 = __ldg(b2 + c0 + 1);
            if (n0r < N)
                *(float2*)(out + (size_t)n0r * 64 + c0) =
                    make_float2(acc2[t][q][0] + bv0, acc2[t][q][1] + bv1);
            if (n1r < N)
                *(float2*)(out + (size_t)n1r * 64 + c0) =
                    make_float2(acc2[t][q][2] + bv0, acc2[t][q][3] + bv1);
        }
    }
}

// ---------------------------------------------------------------------------
// Launch: scatter -> HMMA MLP (MLP restores the zero invariant on g_agg)
// ---------------------------------------------------------------------------
extern "C" void kernel_launch(void* const* d_in, const int* in_sizes, int n_in,
                              void* d_out, int out_size) {
    const float* node_feat = (const float*)d_in[0];
    const float* edge_feat = (const float*)d_in[1];
    const int*   ei        = (const int*)d_in[2];
    const float* W1        = (const float*)d_in[3];
    const float* b1        = (const float*)d_in[4];
    const float* W2        = (const float*)d_in[5];
    const float* b2        = (const float*)d_in[6];
    float* out = (float*)d_out;

    int N = in_sizes[0] / 64;   // 100000
    int E = in_sizes[2] / 2;    // 1200000

    cudaFuncSetAttribute(mlp_mma_kernel, cudaFuncAttributeMaxDynamicSharedMemorySize,
                         SMEM_TOTAL);

    scatter_kernel<<<(E * 16 + 255) / 256, 256>>>(node_feat, edge_feat, ei, E);
    mlp_mma_kernel<<<(N + 127) / 128, MLP_THREADS, SMEM_TOTAL>>>(W1, b1, W2, b2, out, N);
}

// round 13
// speedup vs baseline: 1.4072x; 1.0824x over previous
#include <cuda_runtime.h>
#include <cuda_bf16.h>
#include <cstdint>

#define NN 100000
#define EE 1200000

// Scratch: aggregated messages per node [N, 64]; zero at entry, MLP re-zeroes.
__device__ float g_agg[NN * 64];
// Pre-transposed hi/lo-split weights in smem-tile layout (filled per launch).
__device__ __nv_bfloat16 g_w1s[128 * 136];   // [j][k] hi @k, lo @k+64
__device__ __nv_bfloat16 g_w2s[64 * 264];    // [j][k] hi @k, lo @k+128

// ---------------------------------------------------------------------------
// Kernel 1: scatter-add (best measured variant: 16 threads/edge, RED.v4)
// ---------------------------------------------------------------------------
__global__ void scatter_kernel(const float* __restrict__ node_feat,
                               const float* __restrict__ edge_feat,
                               const int* __restrict__ ei, int E) {
    int gid = blockIdx.x * blockDim.x + threadIdx.x;
    if (gid >= E * 16) return;
    int e = gid >> 4;
    int c = gid & 15;
    int s = __ldg(ei + e);
    int d = __ldg(ei + E + e);
    float4 nf = __ldg(((const float4*)node_feat) + s * 16 + c);
    float4 ef = __ldg(((const float4*)edge_feat) + (size_t)e * 16 + c);
    float4 m = make_float4(nf.x + ef.x, nf.y + ef.y, nf.z + ef.z, nf.w + ef.w);
    float* p = g_agg + (size_t)d * 64 + (c << 2);
    asm volatile("red.global.add.v4.f32 [%0], {%1, %2, %3, %4};"
                 :: "l"(p), "f"(m.x), "f"(m.y), "f"(m.z), "f"(m.w)
                 : "memory");
}

// ---------------------------------------------------------------------------
// Helpers
// ---------------------------------------------------------------------------
__device__ __forceinline__ uint32_t smem_u32(const void* p) {
    uint32_t a;
    asm("{ .reg .u64 t; cvta.to.shared.u64 t, %1; cvt.u32.u64 %0, t; }"
        : "=r"(a) : "l"(p));
    return a;
}

#define LDMX4(d0, d1, d2, d3, addr) \
    asm volatile("ldmatrix.sync.aligned.m8n8.x4.shared.b16 {%0,%1,%2,%3}, [%4];" \
                 : "=r"(d0), "=r"(d1), "=r"(d2), "=r"(d3) : "r"(addr))

#define MMA16816(c, a0, a1, a2, a3, b0, b1) \
    asm volatile("mma.sync.aligned.m16n8k16.row.col.f32.bf16.bf16.f32 " \
                 "{%0,%1,%2,%3}, {%4,%5,%6,%7}, {%8,%9}, {%0,%1,%2,%3};" \
                 : "+f"((c)[0]), "+f"((c)[1]), "+f"((c)[2]), "+f"((c)[3]) \
                 : "r"(a0), "r"(a1), "r"(a2), "r"(a3), "r"(b0), "r"(b1))

// hi/lo split store into shared memory (used for A and H staging)
__device__ __forceinline__ void st_hilo2(uint32_t base, int stride, int row,
                                         int k, int lo_off, float x0, float x1) {
    __nv_bfloat16 h0 = __float2bfloat16(x0), h1 = __float2bfloat16(x1);
    __nv_bfloat16 g0 = __float2bfloat16(x0 - __bfloat162float(h0));
    __nv_bfloat16 g1 = __float2bfloat16(x1 - __bfloat162float(h1));
    uint32_t hw = (uint32_t)__bfloat16_as_ushort(h0) |
                  ((uint32_t)__bfloat16_as_ushort(h1) << 16);
    uint32_t lw = (uint32_t)__bfloat16_as_ushort(g0) |
                  ((uint32_t)__bfloat16_as_ushort(g1) << 16);
    uint32_t a0 = base + (uint32_t)((row * stride + k) * 2);
    uint32_t a1 = base + (uint32_t)((row * stride + k + lo_off) * 2);
    asm volatile("st.shared.b32 [%0], %1;" :: "r"(a0), "r"(hw));
    asm volatile("st.shared.b32 [%0], %1;" :: "r"(a1), "r"(lw));
}

// hi/lo split store into a global bf16 buffer (prep kernel)
__device__ __forceinline__ void g_hilo(__nv_bfloat16* base, int stride, int row,
                                       int k, int lo_off, float x0, float x1) {
    __nv_bfloat16 h0 = __float2bfloat16(x0), h1 = __float2bfloat16(x1);
    base[row * stride + k]     = h0;
    base[row * stride + k + 1] = h1;
    base[row * stride + k + lo_off]     = __float2bfloat16(x0 - __bfloat162float(h0));
    base[row * stride + k + lo_off + 1] = __float2bfloat16(x1 - __bfloat162float(h1));
}

// ---------------------------------------------------------------------------
// Kernel 0: per-launch weight transpose + hi/lo split into global buffers.
// ---------------------------------------------------------------------------
__global__ void prep_w_kernel(const float* __restrict__ W1,
                              const float* __restrict__ W2) {
    int q = blockIdx.x * 256 + threadIdx.x;    // 0..2047
    if (q < 1024) {
        int kp = q & 31, j4 = q >> 5;
        int k0 = kp * 2;
        float4 wa = __ldg(((const float4*)W1) + k0 * 32 + j4);
        float4 wb = __ldg(((const float4*)W1) + (k0 + 1) * 32 + j4);
        int j = j4 * 4;
        g_hilo(g_w1s, 136, j + 0, k0, 64, wa.x, wb.x);
        g_hilo(g_w1s, 136, j + 1, k0, 64, wa.y, wb.y);
        g_hilo(g_w1s, 136, j + 2, k0, 64, wa.z, wb.z);
        g_hilo(g_w1s, 136, j + 3, k0, 64, wa.w, wb.w);
    } else {
        q -= 1024;
        int kp = q & 63, j4 = q >> 6;
        int k0 = kp * 2;
        float4 wa = __ldg(((const float4*)W2) + k0 * 16 + j4);
        float4 wb = __ldg(((const float4*)W2) + (k0 + 1) * 16 + j4);
        int j = j4 * 4;
        g_hilo(g_w2s, 264, j + 0, k0, 128, wa.x, wb.x);
        g_hilo(g_w2s, 264, j + 1, k0, 128, wa.y, wb.y);
        g_hilo(g_w2s, 264, j + 2, k0, 128, wa.z, wb.z);
        g_hilo(g_w2s, 264, j + 3, k0, 128, wa.w, wb.w);
    }
}

// ---------------------------------------------------------------------------
// Kernel 2: HMMA MLP. 128 nodes/block, 256 threads (4m x 2j warp grid).
//   Abuf  [128m][136] bf16: Ahi | Alo                 @ 0      (34816B)
//   W1buf [128j][136] bf16 (memcpy from g_w1s)        @ 34816  (34816B)
//   Hbuf  [128m][264] bf16: Hhi | Hlo                 @ 0      (aliases A+W1)
//   W2buf [64j][264]  bf16 (memcpy from g_w2s)        @ 69632  (33792B)
// ---------------------------------------------------------------------------
#define MLP_THREADS 256
#define AS 136
#define HS 264
#define OFF_A  0u
#define OFF_W1 34816u
#define OFF_W2 69632u
#define SMEM_TOTAL 103424

__global__ void __launch_bounds__(MLP_THREADS, 2) mlp_mma_kernel(
    const float* __restrict__ b1, const float* __restrict__ b2,
    float* __restrict__ out, int N) {
    extern __shared__ char smc[];
    uint32_t sb = smem_u32(smc);
    int tid = threadIdx.x;
    int lane = tid & 31;
    int wid = tid >> 5;
    int node0 = blockIdx.x * 128;

    // ---- stage weights: linear 16B memcpy from pre-split global buffers ----
    {
        const uint4* w1g = (const uint4*)g_w1s;
        uint4* w1smem = (uint4*)(smc + OFF_W1);
#pragma unroll
        for (int i = 0; i < 9; i++) {
            int f = tid + i * 256;
            if (f < 2176) w1smem[f] = __ldg(w1g + f);
        }
        const uint4* w2g = (const uint4*)g_w2s;
        uint4* w2smem = (uint4*)(smc + OFF_W2);
#pragma unroll
        for (int i = 0; i < 9; i++) {
            int f = tid + i * 256;
            if (f < 2112) w2smem[f] = __ldg(w2g + f);
        }
    }
    // ---- stage A (hi|lo) from g_agg; re-zero g_agg ----
#pragma unroll
    for (int i = 0; i < 8; i++) {
        int f = tid + i * 256;
        int r = f >> 4, c4 = f & 15;
        int n = node0 + r;
        float4 v = make_float4(0.f, 0.f, 0.f, 0.f);
        if (n < N) {
            v = __ldg(((const float4*)g_agg) + (size_t)n * 16 + c4);
            ((float4*)g_agg)[(size_t)n * 16 + c4] = make_float4(0.f, 0.f, 0.f, 0.f);
        }
        int k = c4 * 4;
        st_hilo2(sb + OFF_A, AS, r, k,     64, v.x, v.y);
        st_hilo2(sb + OFF_A, AS, r, k + 2, 64, v.z, v.w);
    }
    __syncthreads();

    // Fragment lane offsets (PTX m16n8k16 canonical mappings)
    int rA = (lane & 7) + ((lane >> 3) & 1) * 8;
    int cA = (lane >> 4) * 8;
    int rB = (lane & 7) + (lane >> 4) * 8;
    int cB = ((lane >> 3) & 1) * 8;
    int mw = wid & 3;
    int jw = wid >> 2;
    int m0 = mw * 32;
    int g = lane >> 2;
    int cpair = (lane & 3) * 2;

    // ---------------- GEMM1: D1 = Ahi·Whi + Ahi·Wlo + Alo·Whi ----------------
    float acc[2][8][4];
#pragma unroll
    for (int t = 0; t < 2; t++)
#pragma unroll
        for (int q = 0; q < 8; q++)
#pragma unroll
            for (int p = 0; p < 4; p++) acc[t][q][p] = 0.f;

    int j0 = jw * 64;
#pragma unroll 4
    for (int s = 0; s < 12; s++) {
        int ka = ((s & 3) << 4) + ((s >= 8) ? 64 : 0);
        int kb = ((s & 3) << 4) + ((s >= 4 && s < 8) ? 64 : 0);
        uint32_t a[2][4];
#pragma unroll
        for (int t = 0; t < 2; t++)
            LDMX4(a[t][0], a[t][1], a[t][2], a[t][3],
                  sb + OFF_A + (uint32_t)(((m0 + t * 16 + rA) * AS + ka + cA) * 2));
#pragma unroll
        for (int nt = 0; nt < 4; nt++) {
            uint32_t b0, b1r, b2, b3;
            LDMX4(b0, b1r, b2, b3,
                  sb + OFF_W1 + (uint32_t)(((j0 + nt * 16 + rB) * AS + kb + cB) * 2));
#pragma unroll
            for (int t = 0; t < 2; t++) {
                MMA16816(acc[t][2 * nt],     a[t][0], a[t][1], a[t][2], a[t][3], b0, b1r);
                MMA16816(acc[t][2 * nt + 1], a[t][0], a[t][1], a[t][2], a[t][3], b2, b3);
            }
        }
    }
    __syncthreads();    // Abuf/W1buf dead -> Hbuf may overwrite

    // ---- epilogue 1: +b1, relu, hi/lo split -> Hbuf ----
#pragma unroll
    for (int t = 0; t < 2; t++) {
#pragma unroll
        for (int q = 0; q < 8; q++) {
            int c0 = j0 + q * 8 + cpair;
            float bv0 = __ldg(b1 + c0), bv1 = __ldg(b1 + c0 + 1);
            float x0 = fmaxf(acc[t][q][0] + bv0, 0.f);
            float x1 = fmaxf(acc[t][q][1] + bv1, 0.f);
            float y0 = fmaxf(acc[t][q][2] + bv0, 0.f);
            float y1 = fmaxf(acc[t][q][3] + bv1, 0.f);
            st_hilo2(sb + OFF_A, HS, m0 + t * 16 + g,     c0, 128, x0, x1);
            st_hilo2(sb + OFF_A, HS, m0 + t * 16 + g + 8, c0, 128, y0, y1);
        }
    }
    __syncthreads();

    // ---------------- GEMM2: D2 = Hhi·W2hi + Hlo·W2hi + Hhi·W2lo ----------------
    float acc2[2][4][4];
#pragma unroll
    for (int t = 0; t < 2; t++)
#pragma unroll
        for (int q = 0; q < 4; q++)
#pragma unroll
            for (int p = 0; p < 4; p++) acc2[t][q][p] = 0.f;

    int j0b = jw * 32;
#pragma unroll 4
    for (int s = 0; s < 24; s++) {
        int kh = ((s & 7) << 4) + ((s >= 8 && s < 16) ? 128 : 0);
        int kw = ((s & 7) << 4) + ((s >= 16) ? 128 : 0);
        uint32_t a[2][4];
#pragma unroll
        for (int t = 0; t < 2; t++)
            LDMX4(a[t][0], a[t][1], a[t][2], a[t][3],
                  sb + OFF_A + (uint32_t)(((m0 + t * 16 + rA) * HS + kh + cA) * 2));
#pragma unroll
        for (int nt = 0; nt < 2; nt++) {
            uint32_t b0, b1r, b2, b3;
            LDMX4(b0, b1r, b2, b3,
                  sb + OFF_W2 + (uint32_t)(((j0b + nt * 16 + rB) * HS + kw + cB) * 2));
#pragma unroll
            for (int t = 0; t < 2; t++) {
                MMA16816(acc2[t][2 * nt],     a[t][0], a[t][1], a[t][2], a[t][3], b0, b1r);
                MMA16816(acc2[t][2 * nt + 1], a[t][0], a[t][1], a[t][2], a[t][3], b2, b3);
            }
        }
    }

    // ---- epilogue 2: +b2 -> out ----
#pragma unroll
    for (int t = 0; t < 2; t++) {
        int n0r = node0 + m0 + t * 16 + g;
        int n1r = n0r + 8;
#pragma unroll
        for (int q = 0; q < 4; q++) {
            int c0 = j0b + q * 8 + cpair;
            float bv0 = __ldg(b2 + c0), bv1 = __ldg(b2 + c0 + 1);
            if (n0r < N)
                *(float2*)(out + (size_t)n0r * 64 + c0) =
                    make_float2(acc2[t][q][0] + bv0, acc2[t][q][1] + bv1);
            if (n1r < N)
                *(float2*)(out + (size_t)n1r * 64 + c0) =
                    make_float2(acc2[t][q][2] + bv0, acc2[t][q][3] + bv1);
        }
    }
}

// ---------------------------------------------------------------------------
// Launch: prep weights -> scatter -> HMMA MLP
// ---------------------------------------------------------------------------
extern "C" void kernel_launch(void* const* d_in, const int* in_sizes, int n_in,
                              void* d_out, int out_size) {
    const float* node_feat = (const float*)d_in[0];
    const float* edge_feat = (const float*)d_in[1];
    const int*   ei        = (const int*)d_in[2];
    const float* W1        = (const float*)d_in[3];
    const float* b1        = (const float*)d_in[4];
    const float* W2        = (const float*)d_in[5];
    const float* b2        = (const float*)d_in[6];
    float* out = (float*)d_out;

    int N = in_sizes[0] / 64;   // 100000
    int E = in_sizes[2] / 2;    // 1200000

    cudaFuncSetAttribute(mlp_mma_kernel, cudaFuncAttributeMaxDynamicSharedMemorySize,
                         SMEM_TOTAL);

    prep_w_kernel<<<8, 256>>>(W1, W2);
    scatter_kernel<<<(E * 16 + 255) / 256, 256>>>(node_feat, edge_feat, ei, E);
    mlp_mma_kernel<<<(N + 127) / 128, MLP_THREADS, SMEM_TOTAL>>>(b1, b2, out, N);
}